// round 11
// baseline (speedup 1.0000x reference)
#include <cuda_runtime.h>
#include <math.h>
#include <limits.h>

// Problem shape (fixed by reference setup_inputs)
#define BB_B 32
#define BB_H 512
#define BB_W 512
#define BB_HW (BB_H * BB_W)
#define BB_C 21
#define PPB 128                  // 4 warps per probe block (one per border line)

// Per-(batch,tensor) bbox: {ymin,xmin,ymax,xmax}, ymin==INT_MAX => empty mask.
// Fully rewritten by the probe kernel on every call (both paths), so no reset
// is needed and graph replays are deterministic. Index = batch*2 + tensor.
__device__ int4 g_box[BB_B * 2];

__device__ __forceinline__ float bb_sq(float v) { return v * v; }

__device__ __forceinline__ float bb_penalty(
    float py0, float px0, float py1, float px1, bool hp,
    float ty0, float tx0, float ty1, float tx1, bool ht)
{
    if (!hp) { py0 = 0.f; px0 = 0.f; py1 = 1.f; px1 = 1.f; }
    if (!ht) { ty0 = 0.f; tx0 = 0.f; ty1 = 1.f; tx1 = 1.f; }

    float pa = (py1 - py0 + 1.f) * (px1 - px0 + 1.f);
    float ta = (ty1 - ty0 + 1.f) * (tx1 - tx0 + 1.f);
    float area_pen = fmaxf(pa - ta, 0.f) / (ta + 1.f);

    float co = sqrtf(bb_sq((py0 + py1) * 0.5f - (ty0 + ty1) * 0.5f) +
                     bb_sq((px0 + px1) * 0.5f - (tx0 + tx1) * 0.5f)) / 20.f;

    float iy0 = fmaxf(py0, ty0), ix0 = fmaxf(px0, tx0);
    float iy1 = fminf(py1, ty1), ix1 = fminf(px1, tx1);
    float ia  = fmaxf(0.f, iy1 - iy0 + 1.f) * fmaxf(0.f, ix1 - ix0 + 1.f);
    float ua  = pa + ta - ia + 1e-6f;
    float iou_pen = 1.f - ia / ua;

    return (hp && ht) ? tanhf(area_pen + co + iou_pen) : 0.f;
}

// ---------------------------------------------------------------------------
// Kernel 1: 64 blocks = one per (batch, tensor); 4 warps = 4 border lines,
// one pixel per lane (32 px/line). "Certified masked" iff max(p[1..3]) > p[0]
// (one-sided: true => argmax > 0). All 4 lines certified => this tensor's
// bbox is EXACTLY [0,0,511,511] -> write it directly. Otherwise: exact
// fallback streams this (batch, tensor) plane (correct for any input;
// statistically never taken: P(line uncertified) = 4^-32).
// ---------------------------------------------------------------------------
__global__ __launch_bounds__(PPB) void bb_probe_kernel(
    const float* __restrict__ pred,
    const float* __restrict__ tru)
{
    __shared__ int s_flags;
    __shared__ int s_e[4];

    const int blk  = blockIdx.x;           // batch*2 + tensor
    const int b    = blk >> 1;
    const float* src = (blk & 1) ? tru : pred;
    const int tid  = threadIdx.x;
    const int lane = tid & 31;
    const int warp = tid >> 5;             // = border line

    if (tid == 0) s_flags = 0;
    __syncthreads();

    // ---- probe: warp -> line (0:y=0 1:y=511 2:x=0 3:x=511) ----
    {
        int y, x;
        if      (warp == 0) { y = 0;        x = lane; }
        else if (warp == 1) { y = BB_H - 1; x = lane; }
        else if (warp == 2) { x = 0;        y = lane; }
        else                { x = BB_W - 1; y = lane; }

        const float* p = src + ((size_t)b * BB_HW + (size_t)y * BB_W + x) * BB_C;
        float v0 = __ldg(p);
        float v1 = __ldg(p + 1);
        float v2 = __ldg(p + 2);
        float v3 = __ldg(p + 3);
        bool cert = fmaxf(fmaxf(v1, v2), v3) > v0;

        unsigned bl = __ballot_sync(0xffffffffu, cert);
        if (lane == 0 && bl) atomicOr(&s_flags, 1 << warp);
    }
    __syncthreads();

    if (s_flags == 0xF) {
        if (tid == 0)
            g_box[blk] = make_int4(0, 0, BB_H - 1, BB_W - 1);
        cudaTriggerProgrammaticLaunchCompletion();
        return;
    }

    // ---- exact fallback: stream this (batch, tensor) plane ----
    if (tid < 4) s_e[tid] = (tid < 2) ? INT_MAX : INT_MIN;
    __syncthreads();

    int e0 = INT_MAX, e1 = INT_MAX, e2 = INT_MIN, e3 = INT_MIN;
    for (int idx = tid; idx < BB_HW; idx += PPB) {
        const int y = idx >> 9, x = idx & (BB_W - 1);
        const float* p = src + ((size_t)b * BB_HW + idx) * BB_C;
        float v0 = __ldg(p);
        float mx = __ldg(p + 1);
        #pragma unroll
        for (int c = 2; c < BB_C; ++c) mx = fmaxf(mx, __ldg(p + c));
        if (mx > v0) {
            e0 = min(e0, y); e1 = min(e1, x);
            e2 = max(e2, y); e3 = max(e3, x);
        }
    }
    atomicMin(&s_e[0], e0);
    atomicMin(&s_e[1], e1);
    atomicMax(&s_e[2], e2);
    atomicMax(&s_e[3], e3);
    __syncthreads();
    if (tid == 0)
        g_box[blk] = make_int4(s_e[0], s_e[1], s_e[2], s_e[3]);
    cudaTriggerProgrammaticLaunchCompletion();
}

// ---------------------------------------------------------------------------
// Kernel 2 (PDL): 32 threads; thread b computes batch b's penalty from the
// two boxes, then warp-reduces. Starts during kernel 1; the grid-dependency
// sync provides ordering + visibility of g_box.
// ---------------------------------------------------------------------------
__global__ void bb_reduce_kernel(float* __restrict__ out) {
    cudaGridDependencySynchronize();
    const int b = threadIdx.x;
    int4 pb = g_box[b * 2 + 0];
    int4 tb = g_box[b * 2 + 1];
    bool hp = (pb.x != INT_MAX);
    bool ht = (tb.x != INT_MAX);
    float pen = bb_penalty(
        (float)pb.x, (float)pb.y, (float)pb.z, (float)pb.w, hp,
        (float)tb.x, (float)tb.y, (float)tb.z, (float)tb.w, ht);
    #pragma unroll
    for (int o = 16; o > 0; o >>= 1)
        pen += __shfl_down_sync(0xffffffffu, pen, o);
    if (b == 0) out[0] = 0.05f * (pen / (float)BB_B);
}

extern "C" void kernel_launch(void* const* d_in, const int* in_sizes, int n_in,
                              void* d_out, int out_size)
{
    const float* pred = (const float*)d_in[0];   // prediction_probs [32,512,512,21]
    const float* tru  = (const float*)d_in[1];   // expected_onehot  [32,512,512,21]
    float* out = (float*)d_out;

    bb_probe_kernel<<<BB_B * 2, PPB>>>(pred, tru);   // 64 blocks, one wave

    // Reduce with Programmatic Dependent Launch (overlapped launch).
    cudaLaunchConfig_t cfg = {};
    cfg.gridDim  = dim3(1, 1, 1);
    cfg.blockDim = dim3(32, 1, 1);
    cfg.dynamicSmemBytes = 0;
    cfg.stream = 0;
    cudaLaunchAttribute attr[1];
    attr[0].id = cudaLaunchAttributeProgrammaticStreamSerialization;
    attr[0].val.programmaticStreamSerializationAllowed = 1;
    cfg.attrs = attr;
    cfg.numAttrs = 1;
    cudaLaunchKernelEx(&cfg, bb_reduce_kernel, out);
}

// round 12
// speedup vs baseline: 1.1990x; 1.1990x over previous
#include <cuda_runtime.h>
#include <math.h>
#include <limits.h>

// Problem shape (fixed by reference setup_inputs)
#define BB_B 32
#define BB_H 512
#define BB_W 512
#define BB_HW (BB_H * BB_W)
#define BB_C 21
#define PPB 256                  // 8 warps per block

// Per-batch penalty; fully rewritten by the probe kernel on every call (both
// paths), so no reset is needed and graph replays are deterministic.
__device__ float g_pen[BB_B];

__device__ __forceinline__ float bb_sq(float v) { return v * v; }

__device__ __forceinline__ float bb_penalty(
    float py0, float px0, float py1, float px1, bool hp,
    float ty0, float tx0, float ty1, float tx1, bool ht)
{
    if (!hp) { py0 = 0.f; px0 = 0.f; py1 = 1.f; px1 = 1.f; }
    if (!ht) { ty0 = 0.f; tx0 = 0.f; ty1 = 1.f; tx1 = 1.f; }

    float pa = (py1 - py0 + 1.f) * (px1 - px0 + 1.f);
    float ta = (ty1 - ty0 + 1.f) * (tx1 - tx0 + 1.f);
    float area_pen = fmaxf(pa - ta, 0.f) / (ta + 1.f);

    float co = sqrtf(bb_sq((py0 + py1) * 0.5f - (ty0 + ty1) * 0.5f) +
                     bb_sq((px0 + px1) * 0.5f - (tx0 + tx1) * 0.5f)) / 20.f;

    float iy0 = fmaxf(py0, ty0), ix0 = fmaxf(px0, tx0);
    float iy1 = fminf(py1, ty1), ix1 = fminf(px1, tx1);
    float ia  = fmaxf(0.f, iy1 - iy0 + 1.f) * fmaxf(0.f, ix1 - ix0 + 1.f);
    float ua  = pa + ta - ia + 1e-6f;
    float iou_pen = 1.f - ia / ua;

    return (hp && ht) ? tanhf(area_pen + co + iou_pen) : 0.f;
}

// ---------------------------------------------------------------------------
// Kernel 1: one block per batch, 8 warps = 4 border lines x 2 tensors, one
// pixel per lane (32 px/line). "Certified masked" iff p[1] > p[0] (one-sided:
// true => argmax > 0). If all 8 lines have a certified pixel, both bboxes
// are EXACTLY [0,0,511,511] -> penalty is the constant-folded full-frame
// value. Otherwise: exact in-block full-batch fallback (correct for any
// input; statistically never taken here: P(line uncertified) = 2^-32).
// Each block fires the PDL trigger once its g_pen[b] write is issued.
// ---------------------------------------------------------------------------
__global__ __launch_bounds__(PPB) void bb_probe_kernel(
    const float* __restrict__ pred,
    const float* __restrict__ tru)
{
    __shared__ int s_flags;
    __shared__ int s_e[8];

    const int b    = blockIdx.x;
    const int tid  = threadIdx.x;
    const int lane = tid & 31;
    const int warp = tid >> 5;

    if (tid == 0) s_flags = 0;
    __syncthreads();

    // ---- probe: warp -> (line = warp&3, tensor = warp>>2) ----
    {
        const int line = warp & 3;             // 0:y=0 1:y=511 2:x=0 3:x=511
        const float* src = (warp & 4) ? tru : pred;
        int y, x;
        if      (line == 0) { y = 0;        x = lane; }
        else if (line == 1) { y = BB_H - 1; x = lane; }
        else if (line == 2) { x = 0;        y = lane; }
        else                { x = BB_W - 1; y = lane; }

        const float* p = src + ((size_t)b * BB_HW + (size_t)y * BB_W + x) * BB_C;
        float v0 = __ldg(p);
        float v1 = __ldg(p + 1);
        bool cert = v1 > v0;                   // sound: => argmax > 0

        unsigned bl = __ballot_sync(0xffffffffu, cert);
        if (lane == 0 && bl) atomicOr(&s_flags, 1 << warp);
    }
    __syncthreads();

    if (s_flags == 0xFF) {
        if (tid == 0) {
            // Compile-time constant: full-frame vs full-frame penalty.
            const float H1 = (float)(BB_H - 1), W1 = (float)(BB_W - 1);
            g_pen[b] = bb_penalty(0.f, 0.f, H1, W1, true,
                                  0.f, 0.f, H1, W1, true);
        }
        cudaTriggerProgrammaticLaunchCompletion();
        return;
    }

    // ---- exact fallback: stream the whole batch (rarely/never taken) ----
    if (tid < 8) s_e[tid] = ((tid & 3) < 2) ? INT_MAX : INT_MIN;
    __syncthreads();

    int le[2][4] = {{INT_MAX, INT_MAX, INT_MIN, INT_MIN},
                    {INT_MAX, INT_MAX, INT_MIN, INT_MIN}};
    for (int idx = tid; idx < BB_HW; idx += PPB) {
        const int y = idx >> 9, x = idx & (BB_W - 1);
        #pragma unroll
        for (int t = 0; t < 2; ++t) {
            const float* p = (t ? tru : pred) + ((size_t)b * BB_HW + idx) * BB_C;
            float v0 = __ldg(p);
            float mx = __ldg(p + 1);
            #pragma unroll
            for (int c = 2; c < BB_C; ++c) mx = fmaxf(mx, __ldg(p + c));
            if (mx > v0) {
                le[t][0] = min(le[t][0], y);
                le[t][1] = min(le[t][1], x);
                le[t][2] = max(le[t][2], y);
                le[t][3] = max(le[t][3], x);
            }
        }
    }
    #pragma unroll
    for (int t = 0; t < 2; ++t) {
        atomicMin(&s_e[t * 4 + 0], le[t][0]);
        atomicMin(&s_e[t * 4 + 1], le[t][1]);
        atomicMax(&s_e[t * 4 + 2], le[t][2]);
        atomicMax(&s_e[t * 4 + 3], le[t][3]);
    }
    __syncthreads();
    if (tid == 0) {
        bool hp = (s_e[0] != INT_MAX);
        bool ht = (s_e[4] != INT_MAX);
        g_pen[b] = bb_penalty(
            (float)s_e[0], (float)s_e[1], (float)s_e[2], (float)s_e[3], hp,
            (float)s_e[4], (float)s_e[5], (float)s_e[6], (float)s_e[7], ht);
    }
    cudaTriggerProgrammaticLaunchCompletion();
}

// ---------------------------------------------------------------------------
// Kernel 2 (PDL): one warp reduces the 32 per-batch penalties. Starts while
// kernel 1 runs; cudaGridDependencySynchronize() provides ordering plus
// visibility of kernel 1's g_pen writes.
// ---------------------------------------------------------------------------
__global__ void bb_reduce_kernel(float* __restrict__ out) {
    cudaGridDependencySynchronize();
    const int tid = threadIdx.x;
    float pen = g_pen[tid];
    #pragma unroll
    for (int o = 16; o > 0; o >>= 1)
        pen += __shfl_down_sync(0xffffffffu, pen, o);
    if (tid == 0) out[0] = 0.05f * (pen / (float)BB_B);
}

extern "C" void kernel_launch(void* const* d_in, const int* in_sizes, int n_in,
                              void* d_out, int out_size)
{
    const float* pred = (const float*)d_in[0];   // prediction_probs [32,512,512,21]
    const float* tru  = (const float*)d_in[1];   // expected_onehot  [32,512,512,21]
    float* out = (float*)d_out;

    bb_probe_kernel<<<BB_B, PPB>>>(pred, tru);   // 32 blocks, one wave

    // Reduce with Programmatic Dependent Launch (overlapped launch).
    cudaLaunchConfig_t cfg = {};
    cfg.gridDim  = dim3(1, 1, 1);
    cfg.blockDim = dim3(32, 1, 1);
    cfg.dynamicSmemBytes = 0;
    cfg.stream = 0;
    cudaLaunchAttribute attr[1];
    attr[0].id = cudaLaunchAttributeProgrammaticStreamSerialization;
    attr[0].val.programmaticStreamSerializationAllowed = 1;
    cfg.attrs = attr;
    cfg.numAttrs = 1;
    cudaLaunchKernelEx(&cfg, bb_reduce_kernel, out);
}